// round 4
// baseline (speedup 1.0000x reference)
#include <cuda_runtime.h>
#include <cstdint>

#define N_ROWS   131072
#define DIM      64
#define D2       32           // DIM/2 (f32x2 pairs)
#define K_CODES  1024
#define BM       128          // rows per block tile
#define BKC      64           // codes per chunk
#define THREADS  256
#define TR       8            // rows per thread
#define TC       4            // codes per thread

__device__ float g_csum[K_CODES];
__device__ float g_eT[K_CODES * DIM];   // transposed codebook for gather

typedef unsigned long long ull;

__device__ __forceinline__ ull pack2(float lo, float hi) {
    ull r;
    asm("mov.b64 %0, {%1, %2};" : "=l"(r) : "f"(lo), "f"(hi));
    return r;
}
__device__ __forceinline__ float sum2(ull v) {
    float lo, hi;
    asm("mov.b64 {%0, %1}, %2;" : "=f"(lo), "=f"(hi) : "l"(v));
    return lo + hi;
}
#define FMA2(d, a, b, c) \
    asm("fma.rn.f32x2 %0, %1, %2, %3;" : "=l"(d) : "l"(a), "l"(b), "l"(c))

// ---------------------------------------------------------------------------
// Prep: c[k] = 0.5*||e_k||^2 and transposed codebook g_eT[k][d] = emb[d][k]
// ---------------------------------------------------------------------------
__global__ void vq_prep_kernel(const float* __restrict__ emb) {
    int k = blockIdx.x * blockDim.x + threadIdx.x;
    if (k < K_CODES) {
        float s = 0.0f;
#pragma unroll
        for (int d = 0; d < DIM; d++) {
            float v = emb[d * K_CODES + k];
            s = fmaf(v, v, s);
            g_eT[k * DIM + d] = v;
        }
        g_csum[k] = 0.5f * s;
    }
}

// ---------------------------------------------------------------------------
// Main: register-tiled "GEMM + argmin". Thread tile: 8 rows x 4 codes.
// dist_k = 0.5*||e_k||^2 - f.e_k  (monotonic in true distance)
// ---------------------------------------------------------------------------
__global__ __launch_bounds__(THREADS, 2)
void vq_main_kernel(const float* __restrict__ x,
                    const float* __restrict__ emb,
                    float* __restrict__ out) {
    // 48KB static smem total
    __shared__ __align__(16) ull sxp[D2 * BM];    // 32KB: sxp[d2][row] f32x2
    __shared__ __align__(16) ull sep[D2 * BKC];   // 16KB: sep[d2][code] f32x2

    const int tid = threadIdx.x;
    const int tx  = tid & 15;     // code direction (16 groups of TC=4)
    const int ty  = tid >> 4;     // row direction  (16 groups of TR=8)
    const int rowBase = blockIdx.x * BM;

    // ---- Stage x tile transposed+paired: sxp[d2][row] ----
    {
        const int r = tid >> 1;          // 128 rows, 2 threads per row
        const int h = tid & 1;           // half of the 64 dims
        const float4* xr = reinterpret_cast<const float4*>(
            x + (size_t)(rowBase + r) * DIM) + h * 8;
#pragma unroll
        for (int q = 0; q < 8; q++) {
            float4 v = xr[q];
            int d2 = h * 16 + 2 * q;
            sxp[d2 * BM + r]       = pack2(v.x, v.y);
            sxp[(d2 + 1) * BM + r] = pack2(v.z, v.w);
        }
    }

    float minv[TR];
    int   mink[TR];
#pragma unroll
    for (int r = 0; r < TR; r++) { minv[r] = 3.0e38f; mink[r] = 0; }

    for (int c0 = 0; c0 < K_CODES; c0 += BKC) {
        __syncthreads();   // orders previous compute (and x staging) before restage
        // ---- Stage E chunk: sep[d2][code] = (emb[2d2][k], emb[2d2+1][k]) ----
        {
            const int d2s = tid >> 3;             // 0..31
            const int cb  = (tid & 7) * 8;        // 8 codes each
            const float* e0 = emb + (2 * d2s) * K_CODES + c0 + cb;
            const float* e1 = e0 + K_CODES;
#pragma unroll
            for (int j = 0; j < 8; j++)
                sep[d2s * BKC + cb + j] = pack2(e0[j], e1[j]);
        }
        __syncthreads();

        ull acc[TR][TC];
#pragma unroll
        for (int r = 0; r < TR; r++)
#pragma unroll
            for (int c = 0; c < TC; c++) acc[r][c] = 0ull;

        const ull* xrow = sxp + ty * TR;
        const ull* ecol = sep + tx * TC;

#pragma unroll 1
        for (int d2 = 0; d2 < D2; d2++) {
            ull xf[TR], ef[TC];
            const ull* xp = xrow + d2 * BM;
            const ull* ep = ecol + d2 * BKC;
            // 4x LDS.128, warp-broadcast (2 distinct addrs) -> conflict-free
            *reinterpret_cast<ulonglong2*>(&xf[0]) = *reinterpret_cast<const ulonglong2*>(xp + 0);
            *reinterpret_cast<ulonglong2*>(&xf[2]) = *reinterpret_cast<const ulonglong2*>(xp + 2);
            *reinterpret_cast<ulonglong2*>(&xf[4]) = *reinterpret_cast<const ulonglong2*>(xp + 4);
            *reinterpret_cast<ulonglong2*>(&xf[6]) = *reinterpret_cast<const ulonglong2*>(xp + 6);
            // 2x LDS.128 per thread (16 distinct addrs across warp)
            *reinterpret_cast<ulonglong2*>(&ef[0]) = *reinterpret_cast<const ulonglong2*>(ep + 0);
            *reinterpret_cast<ulonglong2*>(&ef[2]) = *reinterpret_cast<const ulonglong2*>(ep + 2);
#pragma unroll
            for (int r = 0; r < TR; r++)
#pragma unroll
                for (int c = 0; c < TC; c++)
                    FMA2(acc[r][c], xf[r], ef[c], acc[r][c]);
        }

        // fold chunk into running (minv, mink); thread-local ks ascend -> strict <
#pragma unroll
        for (int c = 0; c < TC; c++) {
            const int k = c0 + tx * TC + c;
            const float cs = __ldg(&g_csum[k]);
#pragma unroll
            for (int r = 0; r < TR; r++) {
                float d = cs - sum2(acc[r][c]);
                if (d < minv[r]) { minv[r] = d; mink[r] = k; }
            }
        }
    }

    // ---- Cross-thread argmin reduction (overlay scratch on sep/sxp) ----
    __syncthreads();
    float* rmin = reinterpret_cast<float*>(sep);          // [BM][16]  8KB
    int*   rkid = reinterpret_cast<int*>(sep + 1024);     // [BM][16]  8KB
    int*   kArr = reinterpret_cast<int*>(sxp);            // [BM] final
#pragma unroll
    for (int r = 0; r < TR; r++) {
        int row = ty * TR + r;
        rmin[row * 16 + tx] = minv[r];
        rkid[row * 16 + tx] = mink[r];
    }
    __syncthreads();
    if (tid < BM) {
        float bv = rmin[tid * 16];
        int   bk = rkid[tid * 16];
#pragma unroll
        for (int j = 1; j < 16; j++) {
            float v = rmin[tid * 16 + j];
            int   k = rkid[tid * 16 + j];
            // lexicographic: global first-occurrence tie rule (jnp.argmin)
            if (v < bv || (v == bv && k < bk)) { bv = v; bk = k; }
        }
        kArr[tid] = bk;
    }
    __syncthreads();

    // ---- Gather + store: coalesced float4 from transposed codebook ----
    for (int idx = tid; idx < BM * 16; idx += THREADS) {
        int row = idx >> 4;
        int q   = idx & 15;
        int k   = kArr[row];
        float4 v = *reinterpret_cast<const float4*>(g_eT + (size_t)k * DIM + q * 4);
        *reinterpret_cast<float4*>(out + (size_t)(rowBase + row) * DIM + q * 4) = v;
    }
}

extern "C" void kernel_launch(void* const* d_in, const int* in_sizes, int n_in,
                              void* d_out, int out_size) {
    const float* x   = (const float*)d_in[0];   // [131072, 64]
    const float* emb = (const float*)d_in[1];   // [64, 1024]
    float* out = (float*)d_out;

    vq_prep_kernel<<<4, 256>>>(emb);
    vq_main_kernel<<<N_ROWS / BM, THREADS>>>(x, emb, out);
}